// round 1
// baseline (speedup 1.0000x reference)
#include <cuda_runtime.h>

// out[b, s, d] = x[b, s, d] - sum_d' x[b, s, d']
// x: (8, 8192, 512) fp32 -> 65536 rows of 512 floats.
// One warp per row: each lane holds 4 float4 (16 floats) in registers,
// warp-shuffle reduction for the row sum, subtract, store. Single pass:
// 1 read + 1 write per element, fully coalesced.

static constexpr int D = 512;
static constexpr int VEC_PER_ROW = D / 4;       // 128 float4 per row
static constexpr int VEC_PER_LANE = VEC_PER_ROW / 32;  // 4

__global__ void __launch_bounds__(256, 8)
row_center_kernel(const float4* __restrict__ x, float4* __restrict__ out,
                  int n_rows) {
    const int warp_global = (blockIdx.x * blockDim.x + threadIdx.x) >> 5;
    const int lane = threadIdx.x & 31;
    if (warp_global >= n_rows) return;

    const float4* __restrict__ row = x + (size_t)warp_global * VEC_PER_ROW;
    float4* __restrict__ orow = out + (size_t)warp_global * VEC_PER_ROW;

    float4 v[VEC_PER_LANE];
    float s = 0.0f;
#pragma unroll
    for (int i = 0; i < VEC_PER_LANE; i++) {
        v[i] = row[lane + 32 * i];
        s += (v[i].x + v[i].y) + (v[i].z + v[i].w);
    }

    // warp tree reduction
#pragma unroll
    for (int off = 16; off > 0; off >>= 1)
        s += __shfl_xor_sync(0xffffffffu, s, off);

#pragma unroll
    for (int i = 0; i < VEC_PER_LANE; i++) {
        float4 r = v[i];
        r.x -= s; r.y -= s; r.z -= s; r.w -= s;
        orow[lane + 32 * i] = r;
    }
}

extern "C" void kernel_launch(void* const* d_in, const int* in_sizes, int n_in,
                              void* d_out, int out_size) {
    const float* x = (const float*)d_in[0];
    float* out = (float*)d_out;
    const int n_rows = in_sizes[0] / D;  // 65536

    const int threads = 256;                 // 8 warps/block
    const int warps_per_block = threads / 32;
    const int blocks = (n_rows + warps_per_block - 1) / warps_per_block;

    row_center_kernel<<<blocks, threads>>>(
        (const float4*)x, (float4*)out, n_rows);
}

// round 3
// speedup vs baseline: 1.0108x; 1.0108x over previous
#include <cuda_runtime.h>

// out[b, s, d] = x[b, s, d] - sum_d' x[b, s, d']
// x: (8, 8192, 512) fp32 -> 65536 rows of 512 floats.
// One warp per row; register-resident row; warp-shuffle reduction.
// R2 change: streaming (evict-first) load/store hints — both streams are
// touch-once, so keep them out of L2's retention path.

static constexpr int D = 512;
static constexpr int VEC_PER_ROW = D / 4;              // 128 float4 per row
static constexpr int VEC_PER_LANE = VEC_PER_ROW / 32;  // 4

__global__ void __launch_bounds__(256, 8)
row_center_kernel(const float4* __restrict__ x, float4* __restrict__ out,
                  int n_rows) {
    const int warp_global = (blockIdx.x * blockDim.x + threadIdx.x) >> 5;
    const int lane = threadIdx.x & 31;
    if (warp_global >= n_rows) return;

    const float4* __restrict__ row = x + (size_t)warp_global * VEC_PER_ROW;
    float4* __restrict__ orow = out + (size_t)warp_global * VEC_PER_ROW;

    float4 v[VEC_PER_LANE];
    float s = 0.0f;
#pragma unroll
    for (int i = 0; i < VEC_PER_LANE; i++) {
        v[i] = __ldcs(&row[lane + 32 * i]);   // evict-first streaming load
        s += (v[i].x + v[i].y) + (v[i].z + v[i].w);
    }

    // warp tree reduction
#pragma unroll
    for (int off = 16; off > 0; off >>= 1)
        s += __shfl_xor_sync(0xffffffffu, s, off);

#pragma unroll
    for (int i = 0; i < VEC_PER_LANE; i++) {
        float4 r = v[i];
        r.x -= s; r.y -= s; r.z -= s; r.w -= s;
        __stcs(&orow[lane + 32 * i], r);      // evict-first streaming store
    }
}

extern "C" void kernel_launch(void* const* d_in, const int* in_sizes, int n_in,
                              void* d_out, int out_size) {
    const float* x = (const float*)d_in[0];
    float* out = (float*)d_out;
    const int n_rows = in_sizes[0] / D;  // 65536

    const int threads = 256;  // 8 warps/block
    const int warps_per_block = threads / 32;
    const int blocks = (n_rows + warps_per_block - 1) / warps_per_block;

    row_center_kernel<<<blocks, threads>>>(
        (const float4*)x, (float4*)out, n_rows);
}